// round 17
// baseline (speedup 1.0000x reference)
#include <cuda_runtime.h>
#include <cuda_fp16.h>
#include <math.h>
#include <stdint.h>

#define T_LEN    16384
#define C_CH     8
#define W_WIN    256
#define R_OUT    32
#define NFILT    256
#define ROWS_CTA 1024
#define BLK_ROWS 256
#define XWIN     592
#define PI_D     3.14159265358979323846

// Gabor bank (fp16) pre-laid-out in m16n8k16 B-fragment order:
// u32 index = (((c*16 + q)*4 + i4)*32 + lane)*4 + reg   (256 KB, L2-resident)
__device__ uint32_t g_bfrag[65536];

// ---------------------------------------------------------------------------
// helpers
// ---------------------------------------------------------------------------
__device__ __forceinline__ uint32_t cvt_f16x2(float hi, float lo) {
    uint32_t d;
    asm("cvt.rn.f16x2.f32 %0, %1, %2;" : "=r"(d) : "f"(hi), "f"(lo));
    return d;
}

__device__ __forceinline__ void mma_f16(float* c, const uint32_t* a,
                                        uint32_t b0, uint32_t b1) {
    asm volatile(
        "mma.sync.aligned.m16n8k16.row.col.f32.f16.f16.f32 "
        "{%0,%1,%2,%3}, {%4,%5,%6,%7}, {%8,%9}, {%0,%1,%2,%3};"
        : "+f"(c[0]), "+f"(c[1]), "+f"(c[2]), "+f"(c[3])
        : "r"(a[0]), "r"(a[1]), "r"(a[2]), "r"(a[3]), "r"(b0), "r"(b1));
}

// ---------------------------------------------------------------------------
// Precompute: fp32 Gabor bank (reference-rounding-matched), fp16,
// scattered directly into B-fragment layout.
// ---------------------------------------------------------------------------
__global__ void gabor_precompute_kernel(const float* __restrict__ kV,
                                        const float* __restrict__ sV) {
    int idx = blockIdx.x * blockDim.x + threadIdx.x;    // 65536 = w*256 + f
    if (idx >= W_WIN * NFILT) return;
    int w = idx >> 8;
    int f = idx & 255;
    float k = kV[f];
    float s = sV[f];

    const float c0 = (float)(-2.0 * PI_D / (double)W_WIN);
    float a  = __fmul_rn(c0, k);
    float ph = __fmul_rn(a, (float)w);

    float nm     = (float)w - 128.0f;
    float inv2s2 = 1.0f / (2.0f * s * s);
    float coef   = 1.0f / sqrtf(2.0f * (float)PI_D * s * s);
    float arg    = __fmul_rn(inv2s2, __fmul_rn(nm, nm));
    float g      = __fmul_rn(coef, (float)exp(-(double)arg));

    float fr = __fmul_rn((float)cos((double)ph), g);
    float fi = __fmul_rn((float)sin((double)ph), g);

    int c = f >> 5, j = f & 31;
    int q = w >> 4, kk = w & 15;
    __half* bh = (__half*)g_bfrag;

#pragma unroll
    for (int im = 0; im < 2; im++) {
        float val = im ? fi : fr;
        int n    = 2 * j + im;
        int nt   = n >> 3;
        int lane = ((n & 7) << 2) | ((kk >> 1) & 3);
        int i4   = nt >> 1;
        int reg  = ((nt & 1) << 1) | (kk >> 3);
        int half = kk & 1;
        int u32i = (((c * 16 + q) * 4 + i4) * 32 + lane) * 4 + reg;
        bh[u32i * 2 + half] = __float2half(val);
    }
}

// ---------------------------------------------------------------------------
// Main kernel: CTA = 1024 t-rows of one (b,c), 4 blocks of 256.
// 8 warps = 4 m-positions x 2 n-halves; warp tile m64 x n32.
// Rolling depth-5 diag pipeline: 1 frag build (3 LDS.32) per q-step.
// x window pre-converted to packed fp16 parity copies c0/c1.
// SMEM: B frags 32KB | 2 fp32 x windows | c0 | c1 (bank-shifted)
// ---------------------------------------------------------------------------
#define OFF_XW0  32768
#define OFF_XW1  (OFF_XW0 + XWIN * 4)
#define OFF_C0   (OFF_XW1 + XWIN * 4)
#define OFF_C1   (OFF_C0 + 288 * 4 + 32)
#define SMEM_TOT (OFF_C1 + 288 * 4 + 32)

__global__ void __launch_bounds__(256, 2)
wavelet_mma_kernel(const float* __restrict__ x, float* __restrict__ out) {
    extern __shared__ unsigned char smem[];
    const uint4* __restrict__ bsm = (const uint4*)smem;   // uint4 idx = (q*4+i4)*32 + lane
    uint32_t* c0s = (uint32_t*)(smem + OFF_C0);
    uint32_t* c1s = (uint32_t*)(smem + OFF_C1);

    const int tid   = threadIdx.x;
    const int wi    = tid >> 5;
    const int lane  = tid & 31;
    const int g     = lane >> 2;
    const int mwarp = wi >> 1;          // 0..3 : m position (64 rows each)
    const int nh    = wi & 1;           // 0..1 : n half (4 nt each)
    const int c     = blockIdx.y;
    const int b     = blockIdx.z;
    const int t0    = blockIdx.x * ROWS_CTA;
    const size_t xrow = (size_t)b * T_LEN;

    // Copy this channel's fragment bank (8192 u32 = 2048 uint4), coalesced.
    {
        const uint4* src = (const uint4*)(g_bfrag + c * 8192);
        uint4* dst = (uint4*)smem;
#pragma unroll
        for (int i = 0; i < 8; i++)
            dst[tid + i * 256] = src[tid + i * 256];
    }

    // Window for blk 0: xw0[j] = x[b, t0-128+j, c], zero-padded.
    {
        float* xw0 = (float*)(smem + OFF_XW0);
        for (int j = tid; j < XWIN; j += 256) {
            int t = t0 - 128 + j;
            float v = 0.0f;
            if (t >= 0 && t < T_LEN)
                v = x[(xrow + t) * C_CH + c];
            xw0[j] = v;
        }
    }
    __syncthreads();

    // Thread's fixed parity copy and diag base.
    const uint32_t* __restrict__ cp = (g & 1) ? c1s : c0s;
    const int base0 = mwarp * 64 + g;
    const int ko    = (lane & 3) * 2;
    const int NBLK  = ROWS_CTA / BLK_ROWS;

    for (int blk = 0; blk < NBLK; blk++) {
        const int tb = t0 + blk * BLK_ROWS;
        const float* xcur = (const float*)(smem + (blk & 1 ? OFF_XW1 : OFF_XW0));
        float* xnxt = (float*)(smem + (blk & 1 ? OFF_XW0 : OFF_XW1));

        // Convert window to packed fp16 parity copies.
        for (int i = tid; i < 288; i += 256) {
            float2 v = *(const float2*)(xcur + 2 * i);
            c0s[i] = cvt_f16x2(v.y, v.x);              // (x[2i], x[2i+1])
        }
        for (int i = tid; i < 288; i += 256) {
            float a = xcur[2 * i + 1];
            float d = xcur[2 * i + 2];
            c1s[i] = cvt_f16x2(d, a);                  // (x[2i+1], x[2i+2])
        }
        __syncthreads();

        // Prefetch next blk's window into registers (hidden under q-loop).
        float v0 = 0.0f, v1 = 0.0f, v2 = 0.0f;
        const bool have_next = (blk + 1 < NBLK);
        if (have_next) {
            const int tbn = tb + BLK_ROWS - 128;
            int t = tbn + tid;
            if (t < T_LEN) v0 = x[(xrow + t) * C_CH + c];
            t = tbn + tid + 256;
            if (t < T_LEN) v1 = x[(xrow + t) * C_CH + c];
            if (tid < XWIN - 512) {
                t = tbn + tid + 512;
                if (t < T_LEN) v2 = x[(xrow + t) * C_CH + c];
            }
        }

        float acc[4][4][4];                    // [mt][ntl][r]
#pragma unroll
        for (int mt = 0; mt < 4; mt++)
#pragma unroll
            for (int nt = 0; nt < 4; nt++)
#pragma unroll
                for (int r = 0; r < 4; r++) acc[mt][nt][r] = 0.0f;

        // Rolling diag pipeline: F[s%5] holds frag for diagonal s.
        // Frag = 3 distinct packed words: x[j],x[j+8](=a1=a2),x[j+16].
        uint32_t F[5][4];
#pragma unroll
        for (int s = 0; s < 4; s++) {
            int hb = (base0 + s * 16 + ko) >> 1;
            F[s][0] = cp[hb];
            F[s][1] = cp[hb + 4];
            F[s][2] = F[s][1];
            F[s][3] = cp[hb + 8];
        }

#pragma unroll
        for (int q = 0; q < 16; q++) {
            uint32_t bb[8];
            *(uint4*)(bb)     = bsm[(q * 4 + nh * 2) * 32 + lane];
            *(uint4*)(bb + 4) = bsm[(q * 4 + nh * 2 + 1) * 32 + lane];

            // First n-pair (ntl 0,1).
#pragma unroll
            for (int par = 0; par < 2; par++) {
                uint32_t b0 = bb[par * 2], b1 = bb[par * 2 + 1];
#pragma unroll
                for (int mt = 0; mt < 4; mt++)
                    mma_f16(acc[mt][par], F[(q + mt) % 5], b0, b1);
            }

            // Build diagonal q+4 (consumed next q-step by mt=3 at earliest).
            {
                int hb = (base0 + (q + 4) * 16 + ko) >> 1;
                uint32_t* Fn = F[(q + 4) % 5];
                Fn[0] = cp[hb];
                Fn[1] = cp[hb + 4];
                Fn[2] = Fn[1];
                Fn[3] = cp[hb + 8];
            }

            // Second n-pair (ntl 2,3).
#pragma unroll
            for (int par = 0; par < 2; par++) {
                uint32_t b0 = bb[4 + par * 2], b1 = bb[4 + par * 2 + 1];
#pragma unroll
                for (int mt = 0; mt < 4; mt++)
                    mma_f16(acc[mt][2 + par], F[(q + mt) % 5], b0, b1);
            }
        }

        // Epilogue: power = re^2 + im^2 (re/im = c0/c1 pair of each frag).
#pragma unroll
        for (int mt = 0; mt < 4; mt++) {
#pragma unroll
            for (int u = 0; u < 2; u++) {
                int t = tb + mwarp * 64 + mt * 16 + g + 8 * u;
                size_t ob = (xrow + t) * (size_t)(C_CH * R_OUT) + c * R_OUT;
#pragma unroll
                for (int ntl = 0; ntl < 4; ntl++) {
                    float re = acc[mt][ntl][2 * u];
                    float im = acc[mt][ntl][2 * u + 1];
                    float p = re * re + im * im;
                    int jj = (nh * 4 + ntl) * 4 + (lane & 3);
                    out[ob + 31 - jj] = p;
                }
            }
        }

        // Publish next fp32 window.
        if (have_next) {
            xnxt[tid]       = v0;
            xnxt[tid + 256] = v1;
            if (tid < XWIN - 512) xnxt[tid + 512] = v2;
        }
        __syncthreads();
    }
}

// ---------------------------------------------------------------------------
// Launch
// ---------------------------------------------------------------------------
extern "C" void kernel_launch(void* const* d_in, const int* in_sizes, int n_in,
                              void* d_out, int out_size) {
    const float* x  = (const float*)d_in[0];
    const float* kV = (const float*)d_in[1];
    const float* sV = (const float*)d_in[2];
    float* out = (float*)d_out;

    const int B = in_sizes[0] / (T_LEN * C_CH);

    gabor_precompute_kernel<<<(W_WIN * NFILT + 255) / 256, 256>>>(kV, sV);

    static bool attr_set = false;
    if (!attr_set) {
        cudaFuncSetAttribute(wavelet_mma_kernel,
                             cudaFuncAttributeMaxDynamicSharedMemorySize, SMEM_TOT);
        attr_set = true;
    }

    dim3 grid(T_LEN / ROWS_CTA, C_CH, B);
    wavelet_mma_kernel<<<grid, 256, SMEM_TOT>>>(x, out);
}